// round 14
// baseline (speedup 1.0000x reference)
#include <cuda_runtime.h>
#include <cuda_fp16.h>
#include <cstdint>

#define SEQ 4096
#define HD 64
#define NBATCH 4
#define TN 128
#define NIT 32
#define NTH 256
#define CEXP 0.18033688011112042f  // log2(e)/temperature(8) — folded into Q

#define KSTR 72    // K/V tile row stride in halves (144B)

// ---- phase B smem (half offsets): ring-3 K + ring-3 V ----
#define H_K 0                // 3 rings of 128*72 = 9216
#define H_V 27648            // 3 rings of 9216 (slot 0 doubles as Q staging)
#define H_TOTB 55296
#define SMEMB_BYTES (H_TOTB * 2)

// ---- phase A smem (half offsets) ----
#define HA_Q 0               // 64*72 = 4608 halves
#define HA_K 4608            // 4 rings of 9216
#define HA_TOT 41472
#define SMEMA_BYTES (HA_TOT * 2 + 64 * 4)

__device__ __half g_QH[NBATCH * SEQ * HD];
__device__ __half g_KH[NBATCH * SEQ * HD];
__device__ __half g_VH[NBATCH * SEQ * HD];
__device__ float g_RS[NBATCH * SEQ];

__device__ __forceinline__ uint32_t f2h2(float x, float y) {
    __half2 h = __floats2half2_rn(x, y);
    return *reinterpret_cast<uint32_t*>(&h);
}
__device__ __forceinline__ void ldsm4(uint32_t& r0, uint32_t& r1, uint32_t& r2,
                                      uint32_t& r3, uint32_t addr) {
    asm volatile("ldmatrix.sync.aligned.m8n8.x4.shared.b16 {%0,%1,%2,%3}, [%4];"
                 : "=r"(r0), "=r"(r1), "=r"(r2), "=r"(r3) : "r"(addr));
}
__device__ __forceinline__ void ldsm4t(uint32_t& r0, uint32_t& r1, uint32_t& r2,
                                       uint32_t& r3, uint32_t addr) {
    asm volatile("ldmatrix.sync.aligned.m8n8.x4.trans.shared.b16 {%0,%1,%2,%3}, [%4];"
                 : "=r"(r0), "=r"(r1), "=r"(r2), "=r"(r3) : "r"(addr));
}
__device__ __forceinline__ void mma16(float c[4], const uint32_t a[4], uint32_t b0,
                                      uint32_t b1) {
    asm volatile(
        "mma.sync.aligned.m16n8k16.row.col.f32.f16.f16.f32 "
        "{%0,%1,%2,%3}, {%4,%5,%6,%7}, {%8,%9}, {%0,%1,%2,%3};\n"
        : "+f"(c[0]), "+f"(c[1]), "+f"(c[2]), "+f"(c[3])
        : "r"(a[0]), "r"(a[1]), "r"(a[2]), "r"(a[3]), "r"(b0), "r"(b1));
}
__device__ __forceinline__ void mma16_z(float d[4], const uint32_t a[4], uint32_t b0,
                                        uint32_t b1) {
    asm volatile(
        "mma.sync.aligned.m16n8k16.row.col.f32.f16.f16.f32 "
        "{%0,%1,%2,%3}, {%4,%5,%6,%7}, {%8,%9}, {%10,%10,%10,%10};\n"
        : "=f"(d[0]), "=f"(d[1]), "=f"(d[2]), "=f"(d[3])
        : "r"(a[0]), "r"(a[1]), "r"(a[2]), "r"(a[3]), "r"(b0), "r"(b1), "f"(0.f));
}
__device__ __forceinline__ void cpa16(uint32_t dst, const __half* src) {
    asm volatile("cp.async.cg.shared.global [%0], [%1], 16;" ::"r"(dst), "l"(src));
}
#define CP_COMMIT() asm volatile("cp.async.commit_group;" ::: "memory")
#define CP_WAIT(n) asm volatile("cp.async.wait_group %0;" ::"n"(n) : "memory")

// ---- pre-pass: fp32 -> fp16; Q pre-scaled by log2(e)/temperature ----
__global__ void __launch_bounds__(256) cvt_kernel(const float* __restrict__ q,
                                                  const float* __restrict__ k,
                                                  const float* __restrict__ v) {
    int i = (blockIdx.x * 256 + threadIdx.x) * 4;
    float4 a = *reinterpret_cast<const float4*>(q + i);
    float4 bk = *reinterpret_cast<const float4*>(k + i);
    float4 c = *reinterpret_cast<const float4*>(v + i);
    *reinterpret_cast<uint2*>(&g_QH[i]) =
        make_uint2(f2h2(a.x * CEXP, a.y * CEXP), f2h2(a.z * CEXP, a.w * CEXP));
    *reinterpret_cast<uint2*>(&g_KH[i]) = make_uint2(f2h2(bk.x, bk.y), f2h2(bk.z, bk.w));
    *reinterpret_cast<uint2*>(&g_VH[i]) = make_uint2(f2h2(c.x, c.y), f2h2(c.z, c.w));
}

// ================= Kernel A: rowsums of exp (2 CTAs/SM) =================
__global__ void __launch_bounds__(128, 2) attn_sums_k() {
    extern __shared__ __half sh[];
    float* RS = reinterpret_cast<float*>(sh + HA_TOT);
    const uint32_t smb = (uint32_t)__cvta_generic_to_shared(sh);

    const int tid = threadIdx.x, w = tid >> 5, lane = tid & 31;
    const int g = lane >> 2, tg = lane & 3;
    const int lr3 = lane & 7, b3 = (lane >> 3) & 1, b4 = (lane >> 4) & 1;
    const int b = blockIdx.x >> 6;
    const int q0 = (blockIdx.x & 63) << 6;
    const int wq = (w >> 1) * 32;
    const int wnq = (w & 1) * 64;

    const uint32_t kq_off = (uint32_t)(wnq + b4 * 8 + lr3) * 144u + (uint32_t)b3 * 16u;
    const uint32_t pa72 = (uint32_t)(b3 * 8 + lr3) * 144u + (uint32_t)b4 * 16u;

    const __half* Qh = g_QH + ((size_t)b * SEQ + q0) * HD;
    const __half* Kh = g_KH + (size_t)b * SEQ * HD;

    if (tid < 64) RS[tid] = 0.f;

    auto stageK = [&](int slot, const __half* src) {
#pragma unroll
        for (int t = 0; t < 8; ++t) {
            int ci = tid + t * 128;
            int row = ci >> 3, c8 = ci & 7;
            cpa16(smb + 2u * (uint32_t)(HA_K + slot * 9216 + row * KSTR) +
                      (uint32_t)c8 * 16u,
                  src + row * HD + c8 * 8);
        }
    };
#pragma unroll
    for (int t = 0; t < 4; ++t) {
        int ci = tid + t * 128;
        int row = ci >> 3, c8 = ci & 7;
        cpa16(smb + 2u * (uint32_t)(HA_Q + row * KSTR) + (uint32_t)c8 * 16u,
              Qh + row * HD + c8 * 8);
    }
    CP_COMMIT();
    stageK(0, Kh);
    CP_COMMIT();
    stageK(1, Kh + TN * HD);
    CP_COMMIT();
    CP_WAIT(0);
    __syncthreads();

    uint32_t qf[4][2][4];
#pragma unroll
    for (int kk = 0; kk < 4; ++kk)
#pragma unroll
        for (int i = 0; i < 2; ++i)
            ldsm4(qf[kk][i][0], qf[kk][i][1], qf[kk][i][2], qf[kk][i][3],
                  smb + 2u * HA_Q + (uint32_t)(wq + i * 16) * 144u + pa72 + kk * 32u);

    const uint32_t kBA[4] = {
        smb + 2u * (HA_K + 0 * 9216), smb + 2u * (HA_K + 1 * 9216),
        smb + 2u * (HA_K + 2 * 9216), smb + 2u * (HA_K + 3 * 9216)};

    float c[2][8][4];
    auto qk_issue = [&](uint32_t kbuf) {
#pragma unroll
        for (int kk = 0; kk < 4; ++kk) {
#pragma unroll
            for (int j2 = 0; j2 < 8; j2 += 2) {
                uint32_t b0, b1, b2_, b3_;
                ldsm4(b0, b1, b2_, b3_, kbuf + kq_off + (uint32_t)j2 * 1152u + kk * 32u);
                if (kk == 0) {
                    mma16_z(c[0][j2], qf[0][0], b0, b1);
                    mma16_z(c[1][j2], qf[0][1], b0, b1);
                    mma16_z(c[0][j2 + 1], qf[0][0], b2_, b3_);
                    mma16_z(c[1][j2 + 1], qf[0][1], b2_, b3_);
                } else {
                    mma16(c[0][j2], qf[kk][0], b0, b1);
                    mma16(c[1][j2], qf[kk][1], b0, b1);
                    mma16(c[0][j2 + 1], qf[kk][0], b2_, b3_);
                    mma16(c[1][j2 + 1], qf[kk][1], b2_, b3_);
                }
            }
        }
    };

    float rsum[2][2] = {{0.f, 0.f}, {0.f, 0.f}};
    qk_issue(kBA[0]);
    for (int it = 0; it < NIT; ++it) {
        if (it + 2 < NIT) {
            stageK((it + 2) & 3, Kh + (it + 2) * TN * HD);
            CP_COMMIT();
        }
#pragma unroll
        for (int i = 0; i < 2; ++i)
#pragma unroll
            for (int j = 0; j < 8; ++j) {
                rsum[i][0] += exp2f(c[i][j][0]) + exp2f(c[i][j][1]);
                rsum[i][1] += exp2f(c[i][j][2]) + exp2f(c[i][j][3]);
            }
        if (it + 2 < NIT) CP_WAIT(1); else CP_WAIT(0);
        __syncthreads();
        if (it + 1 < NIT) qk_issue(kBA[(it + 1) & 3]);
    }
#pragma unroll
    for (int i = 0; i < 2; ++i)
#pragma unroll
        for (int h = 0; h < 2; ++h) {
            float v = rsum[i][h];
            v += __shfl_xor_sync(0xffffffffu, v, 1);
            v += __shfl_xor_sync(0xffffffffu, v, 2);
            if (tg == 0) atomicAdd(&RS[wq + i * 16 + h * 8 + g], v);
        }
    __syncthreads();
    if (tid < 64) g_RS[b * SEQ + q0 + tid] = RS[tid];
}

// ========== Kernel B: attn + AV, TQ=64, 2 CTAs/SM, ring-3 K/V ==========
__global__ void __launch_bounds__(NTH, 2)
attn_fused(float* __restrict__ outp, float* __restrict__ attnp) {
    extern __shared__ __half sh[];
    const uint32_t smb = (uint32_t)__cvta_generic_to_shared(sh);

    const int tid = threadIdx.x, w = tid >> 5, lane = tid & 31;
    const int g = lane >> 2, tg = lane & 3;
    const int lr3 = lane & 7, b3 = (lane >> 3) & 1, b4 = (lane >> 4) & 1;
    const int b = blockIdx.x >> 6;
    const int q0 = (blockIdx.x & 63) << 6;   // 64-row q tile
    const int wq = (w >> 1) * 16;            // 4 q-groups of 16 rows
    const int wnq = (w & 1) * 64;            // 2 n-groups of 64 cols

    const uint32_t kq_off = (uint32_t)(wnq + b4 * 8 + lr3) * 144u + (uint32_t)b3 * 16u;
    const uint32_t pa72 = (uint32_t)(b3 * 8 + lr3) * 144u + (uint32_t)b4 * 16u;
    const uint32_t va_off = (uint32_t)(wnq + b3 * 8 + lr3) * 144u + (uint32_t)b4 * 16u;

    const __half* Qh = g_QH + ((size_t)b * SEQ + q0) * HD;
    const __half* Kh = g_KH + (size_t)b * SEQ * HD;
    const __half* Vh = g_VH + (size_t)b * SEQ * HD;

    // stage a 128x64 fp16 tile via cp.async; perm applies tau (round-12 layout)
    auto stage = [&](uint32_t hbase, const __half* gsrc) {
#pragma unroll
        for (int t = 0; t < 4; ++t) {
            int ci = tid + t * NTH;
            int row = ci >> 3, c8 = ci & 7;
            int r = row & 15;
            int srow = (row & 112) | (r & 1) | (((r >> 3) & 1) << 1) |
                       (((r >> 1) & 3) << 2);
            cpa16(smb + 2u * (uint32_t)(hbase + row * KSTR) + (uint32_t)c8 * 16u,
                  gsrc + srow * HD + c8 * 8);
        }
    };

    // ---- prologue: Q (into V slot 0, unpermuted, 64 rows) + K0/K1 ----
#pragma unroll
    for (int t = 0; t < 2; ++t) {
        int ci = tid + t * NTH;
        int row = ci >> 3, c8 = ci & 7;
        cpa16(smb + 2u * (uint32_t)(H_V + row * KSTR) + (uint32_t)c8 * 16u,
              Qh + row * HD + c8 * 8);
    }
    CP_COMMIT();
    stage(H_K + 0 * 9216, Kh);
    CP_COMMIT();
    stage(H_K + 1 * 9216, Kh + TN * HD);
    CP_COMMIT();
    CP_WAIT(1);  // Q + K0 landed
    __syncthreads();

    // hoist Q fragments (16-row warp tile)
    uint32_t qf[4][4];
#pragma unroll
    for (int kk = 0; kk < 4; ++kk)
        ldsm4(qf[kk][0], qf[kk][1], qf[kk][2], qf[kk][3],
              smb + 2u * H_V + (uint32_t)wq * 144u + pa72 + kk * 32u);

    float lr[2];
#pragma unroll
    for (int h = 0; h < 2; ++h)
        lr[h] = -log2f(g_RS[b * SEQ + q0 + wq + h * 8 + g]);

    __syncthreads();  // Q region dead before V0 staged
    stage(H_V + 0 * 9216, Vh);
    CP_COMMIT();
    stage(H_V + 1 * 9216, Vh + TN * HD);
    CP_COMMIT();
    CP_WAIT(0);
    __syncthreads();

    float c[8][4];
    auto qk_issue = [&](uint32_t kbuf) {
#pragma unroll
        for (int kk = 0; kk < 4; ++kk) {
#pragma unroll
            for (int j2 = 0; j2 < 8; j2 += 2) {
                uint32_t b0, b1, b2_, b3_;
                ldsm4(b0, b1, b2_, b3_, kbuf + kq_off + (uint32_t)j2 * 1152u + kk * 32u);
                if (kk == 0) {
                    mma16_z(c[j2], qf[0], b0, b1);
                    mma16_z(c[j2 + 1], qf[0], b2_, b3_);
                } else {
                    mma16(c[j2], qf[kk], b0, b1);
                    mma16(c[j2 + 1], qf[kk], b2_, b3_);
                }
            }
        }
    };

    float o[8][4] = {};
    qk_issue(smb + 2u * (H_K + 0 * 9216));

    int sCur = 0;
    for (int it = 0; it < NIT; ++it) {
        const int n0 = it * TN;
        const int sNxt = (sCur + 1 == 3) ? 0 : sCur + 1;
        const int sStg = (sNxt + 1 == 3) ? 0 : sNxt + 1;
        // --- pre-barrier: stage K(it+2), exp + attn STG.128, pack P ---
        if (it + 2 < NIT) {
            stage(H_K + sStg * 9216, Kh + (it + 2) * TN * HD);
            CP_COMMIT();
        }
        {
            const int row = q0 + wq + g;
            float* ar0 = attnp + ((size_t)b * SEQ + row) * SEQ + n0 + wnq + 4 * tg;
            float* ar1 = ar0 + (size_t)8 * SEQ;
#pragma unroll
            for (int jp = 0; jp < 4; ++jp) {
                c[2 * jp][0] = exp2f(c[2 * jp][0] + lr[0]);
                c[2 * jp][1] = exp2f(c[2 * jp][1] + lr[0]);
                c[2 * jp][2] = exp2f(c[2 * jp][2] + lr[1]);
                c[2 * jp][3] = exp2f(c[2 * jp][3] + lr[1]);
                c[2 * jp + 1][0] = exp2f(c[2 * jp + 1][0] + lr[0]);
                c[2 * jp + 1][1] = exp2f(c[2 * jp + 1][1] + lr[0]);
                c[2 * jp + 1][2] = exp2f(c[2 * jp + 1][2] + lr[1]);
                c[2 * jp + 1][3] = exp2f(c[2 * jp + 1][3] + lr[1]);
                __stcs(reinterpret_cast<float4*>(ar0 + 16 * jp),
                       make_float4(c[2 * jp][0], c[2 * jp][1],
                                   c[2 * jp + 1][0], c[2 * jp + 1][1]));
                __stcs(reinterpret_cast<float4*>(ar1 + 16 * jp),
                       make_float4(c[2 * jp][2], c[2 * jp][3],
                                   c[2 * jp + 1][2], c[2 * jp + 1][3]));
            }
        }
        uint32_t a[4][4];
#pragma unroll
        for (int kk = 0; kk < 4; ++kk) {
            a[kk][0] = f2h2(c[2 * kk][0], c[2 * kk][1]);
            a[kk][1] = f2h2(c[2 * kk][2], c[2 * kk][3]);
            a[kk][2] = f2h2(c[2 * kk + 1][0], c[2 * kk + 1][1]);
            a[kk][3] = f2h2(c[2 * kk + 1][2], c[2 * kk + 1][3]);
        }
        if (it + 2 < NIT) CP_WAIT(2);
        else if (it + 1 < NIT) CP_WAIT(1);
        else CP_WAIT(0);
        __syncthreads();
        // --- post-barrier: next QK (c dead), AV fills latency, V staged last ---
        if (it + 1 < NIT) qk_issue(smb + 2u * (H_K + sNxt * 9216));
        const uint32_t vb = smb + 2u * (H_V + sCur * 9216);
#pragma unroll
        for (int kk = 0; kk < 4; ++kk) {
#pragma unroll
            for (int j = 0; j < 4; ++j) {
                uint32_t b0, b1, b2_, b3_;
                ldsm4t(b0, b1, b2_, b3_, vb + va_off + (uint32_t)kk * 2304u + j * 32u);
                mma16(o[2 * j], a[kk], b0, b1);
                mma16(o[2 * j + 1], a[kk], b2_, b3_);
            }
        }
        if (it + 2 < NIT) {
            stage(H_V + sStg * 9216, Vh + (it + 2) * TN * HD);
            CP_COMMIT();
        }
        sCur = sNxt;
    }

    // ---- epilogue: reduce partial O across the 2 n-groups, write out ----
    float* FS = reinterpret_cast<float*>(sh);  // reuse K ring
    const int qg = w >> 1;
    __syncthreads();
    if (w & 1) {
#pragma unroll
        for (int j = 0; j < 8; ++j) {
            const int col = j * 8 + 2 * tg;
            *reinterpret_cast<float2*>(&FS[qg * 1024 + g * 64 + col]) =
                make_float2(o[j][0], o[j][1]);
            *reinterpret_cast<float2*>(&FS[qg * 1024 + (8 + g) * 64 + col]) =
                make_float2(o[j][2], o[j][3]);
        }
    }
    __syncthreads();
    if (!(w & 1)) {
        const int row = q0 + wq + g;
        float* orow = outp + ((size_t)b * SEQ + row) * HD;
#pragma unroll
        for (int j = 0; j < 8; ++j) {
            const int col = j * 8 + 2 * tg;
            float2 p0 = *reinterpret_cast<float2*>(&FS[qg * 1024 + g * 64 + col]);
            float2 p1 = *reinterpret_cast<float2*>(&FS[qg * 1024 + (8 + g) * 64 + col]);
            *reinterpret_cast<float2*>(orow + col) =
                make_float2(o[j][0] + p0.x, o[j][1] + p0.y);
            *reinterpret_cast<float2*>(orow + 8 * HD + col) =
                make_float2(o[j][2] + p1.x, o[j][3] + p1.y);
        }
    }
}

extern "C" void kernel_launch(void* const* d_in, const int* in_sizes, int n_in,
                              void* d_out, int out_size) {
    const float* q = (const float*)d_in[0];
    const float* k = (const float*)d_in[1];
    const float* v = (const float*)d_in[2];
    float* outp = (float*)d_out;
    float* attnp = outp + (size_t)NBATCH * SEQ * HD;

    cvt_kernel<<<NBATCH * SEQ * HD / (256 * 4), 256>>>(q, k, v);

    cudaFuncSetAttribute(attn_sums_k, cudaFuncAttributeMaxDynamicSharedMemorySize,
                         SMEMA_BYTES);
    cudaFuncSetAttribute(attn_fused, cudaFuncAttributeMaxDynamicSharedMemorySize,
                         SMEMB_BYTES);

    attn_sums_k<<<NBATCH * 64, 128, SMEMA_BYTES>>>();
    attn_fused<<<NBATCH * 64, NTH, SMEMB_BYTES>>>(outp, attnp);
}

// round 15
// speedup vs baseline: 1.0280x; 1.0280x over previous
#include <cuda_runtime.h>
#include <cuda_fp16.h>
#include <cstdint>

#define SEQ 4096
#define HD 64
#define NBATCH 4
#define TN 128
#define NIT 32
#define NTH 256
#define CEXP 0.18033688011112042f  // log2(e)/temperature(8) — folded into Q

#define KSTR 72    // K/V tile row stride in halves (144B)

// ---- phase B smem (half offsets): ring-4 K + ring-4 V ----
#define H_K 0                // 4 rings of 128*72 = 9216
#define H_V 36864            // 4 rings of 9216 (slot 0 doubles as Q staging)
#define H_TOT 73728
#define SMEMB_BYTES (H_TOT * 2 + 128 * 4)

// ---- phase A smem (half offsets) ----
#define HA_Q 0               // 64*72 = 4608 halves
#define HA_K 4608            // 4 rings of 9216
#define HA_TOT 41472
#define SMEMA_BYTES (HA_TOT * 2 + 64 * 4)

__device__ __half g_QH[NBATCH * SEQ * HD];
__device__ __half g_KH[NBATCH * SEQ * HD];
__device__ __half g_VH[NBATCH * SEQ * HD];
__device__ float g_RS[NBATCH * SEQ];

__device__ __forceinline__ uint32_t f2h2(float x, float y) {
    __half2 h = __floats2half2_rn(x, y);
    return *reinterpret_cast<uint32_t*>(&h);
}
__device__ __forceinline__ void ldsm4(uint32_t& r0, uint32_t& r1, uint32_t& r2,
                                      uint32_t& r3, uint32_t addr) {
    asm volatile("ldmatrix.sync.aligned.m8n8.x4.shared.b16 {%0,%1,%2,%3}, [%4];"
                 : "=r"(r0), "=r"(r1), "=r"(r2), "=r"(r3) : "r"(addr));
}
__device__ __forceinline__ void ldsm4t(uint32_t& r0, uint32_t& r1, uint32_t& r2,
                                       uint32_t& r3, uint32_t addr) {
    asm volatile("ldmatrix.sync.aligned.m8n8.x4.trans.shared.b16 {%0,%1,%2,%3}, [%4];"
                 : "=r"(r0), "=r"(r1), "=r"(r2), "=r"(r3) : "r"(addr));
}
__device__ __forceinline__ void mma16(float c[4], const uint32_t a[4], uint32_t b0,
                                      uint32_t b1) {
    asm volatile(
        "mma.sync.aligned.m16n8k16.row.col.f32.f16.f16.f32 "
        "{%0,%1,%2,%3}, {%4,%5,%6,%7}, {%8,%9}, {%0,%1,%2,%3};\n"
        : "+f"(c[0]), "+f"(c[1]), "+f"(c[2]), "+f"(c[3])
        : "r"(a[0]), "r"(a[1]), "r"(a[2]), "r"(a[3]), "r"(b0), "r"(b1));
}
__device__ __forceinline__ void mma16_z(float d[4], const uint32_t a[4], uint32_t b0,
                                        uint32_t b1) {
    asm volatile(
        "mma.sync.aligned.m16n8k16.row.col.f32.f16.f16.f32 "
        "{%0,%1,%2,%3}, {%4,%5,%6,%7}, {%8,%9}, {%10,%10,%10,%10};\n"
        : "=f"(d[0]), "=f"(d[1]), "=f"(d[2]), "=f"(d[3])
        : "r"(a[0]), "r"(a[1]), "r"(a[2]), "r"(a[3]), "r"(b0), "r"(b1), "f"(0.f));
}
__device__ __forceinline__ void cpa16(uint32_t dst, const __half* src) {
    asm volatile("cp.async.cg.shared.global [%0], [%1], 16;" ::"r"(dst), "l"(src));
}
#define CP_COMMIT() asm volatile("cp.async.commit_group;" ::: "memory")
#define CP_WAIT(n) asm volatile("cp.async.wait_group %0;" ::"n"(n) : "memory")

// ---- pre-pass: fp32 -> fp16; Q pre-scaled by log2(e)/temperature ----
__global__ void __launch_bounds__(256) cvt_kernel(const float* __restrict__ q,
                                                  const float* __restrict__ k,
                                                  const float* __restrict__ v) {
    int i = (blockIdx.x * 256 + threadIdx.x) * 4;
    float4 a = *reinterpret_cast<const float4*>(q + i);
    float4 bk = *reinterpret_cast<const float4*>(k + i);
    float4 c = *reinterpret_cast<const float4*>(v + i);
    *reinterpret_cast<uint2*>(&g_QH[i]) =
        make_uint2(f2h2(a.x * CEXP, a.y * CEXP), f2h2(a.z * CEXP, a.w * CEXP));
    *reinterpret_cast<uint2*>(&g_KH[i]) = make_uint2(f2h2(bk.x, bk.y), f2h2(bk.z, bk.w));
    *reinterpret_cast<uint2*>(&g_VH[i]) = make_uint2(f2h2(c.x, c.y), f2h2(c.z, c.w));
}

// ===== Kernel A: rowsums of exp (2 CTAs/SM, double-buffered scores) =====
__global__ void __launch_bounds__(128, 2) attn_sums_k() {
    extern __shared__ __half sh[];
    float* RS = reinterpret_cast<float*>(sh + HA_TOT);
    const uint32_t smb = (uint32_t)__cvta_generic_to_shared(sh);

    const int tid = threadIdx.x, w = tid >> 5, lane = tid & 31;
    const int g = lane >> 2, tg = lane & 3;
    const int lr3 = lane & 7, b3 = (lane >> 3) & 1, b4 = (lane >> 4) & 1;
    const int b = blockIdx.x >> 6;
    const int q0 = (blockIdx.x & 63) << 6;
    const int wq = (w >> 1) * 32;
    const int wnq = (w & 1) * 64;

    const uint32_t kq_off = (uint32_t)(wnq + b4 * 8 + lr3) * 144u + (uint32_t)b3 * 16u;
    const uint32_t pa72 = (uint32_t)(b3 * 8 + lr3) * 144u + (uint32_t)b4 * 16u;

    const __half* Qh = g_QH + ((size_t)b * SEQ + q0) * HD;
    const __half* Kh = g_KH + (size_t)b * SEQ * HD;

    if (tid < 64) RS[tid] = 0.f;

    auto stageK = [&](int slot, const __half* src) {
#pragma unroll
        for (int t = 0; t < 8; ++t) {
            int ci = tid + t * 128;
            int row = ci >> 3, c8 = ci & 7;
            cpa16(smb + 2u * (uint32_t)(HA_K + slot * 9216 + row * KSTR) +
                      (uint32_t)c8 * 16u,
                  src + row * HD + c8 * 8);
        }
    };
#pragma unroll
    for (int t = 0; t < 4; ++t) {
        int ci = tid + t * 128;
        int row = ci >> 3, c8 = ci & 7;
        cpa16(smb + 2u * (uint32_t)(HA_Q + row * KSTR) + (uint32_t)c8 * 16u,
              Qh + row * HD + c8 * 8);
    }
    CP_COMMIT();
    stageK(0, Kh);
    CP_COMMIT();
    stageK(1, Kh + TN * HD);
    CP_COMMIT();
    CP_WAIT(0);
    __syncthreads();

    uint32_t qf[4][2][4];
#pragma unroll
    for (int kk = 0; kk < 4; ++kk)
#pragma unroll
        for (int i = 0; i < 2; ++i)
            ldsm4(qf[kk][i][0], qf[kk][i][1], qf[kk][i][2], qf[kk][i][3],
                  smb + 2u * HA_Q + (uint32_t)(wq + i * 16) * 144u + pa72 + kk * 32u);

    const uint32_t kBA[4] = {
        smb + 2u * (HA_K + 0 * 9216), smb + 2u * (HA_K + 1 * 9216),
        smb + 2u * (HA_K + 2 * 9216), smb + 2u * (HA_K + 3 * 9216)};

    float cA[2][8][4], cB[2][8][4];
    auto qk_issue = [&](float (&c)[2][8][4], uint32_t kbuf) {
#pragma unroll
        for (int kk = 0; kk < 4; ++kk) {
#pragma unroll
            for (int j2 = 0; j2 < 8; j2 += 2) {
                uint32_t b0, b1, b2_, b3_;
                ldsm4(b0, b1, b2_, b3_, kbuf + kq_off + (uint32_t)j2 * 1152u + kk * 32u);
                if (kk == 0) {
                    mma16_z(c[0][j2], qf[0][0], b0, b1);
                    mma16_z(c[1][j2], qf[0][1], b0, b1);
                    mma16_z(c[0][j2 + 1], qf[0][0], b2_, b3_);
                    mma16_z(c[1][j2 + 1], qf[0][1], b2_, b3_);
                } else {
                    mma16(c[0][j2], qf[kk][0], b0, b1);
                    mma16(c[1][j2], qf[kk][1], b0, b1);
                    mma16(c[0][j2 + 1], qf[kk][0], b2_, b3_);
                    mma16(c[1][j2 + 1], qf[kk][1], b2_, b3_);
                }
            }
        }
    };

    float rsum[2][2] = {{0.f, 0.f}, {0.f, 0.f}};
    qk_issue(cA, kBA[0]);

    // loop: stage(it+2) -> wait -> barrier -> qk(it+1) into cn -> exp(cc)
    auto bodyA = [&](int it, float (&cc)[2][8][4], float (&cn)[2][8][4]) {
        if (it + 2 < NIT) {
            stageK((it + 2) & 3, Kh + (it + 2) * TN * HD);
            CP_COMMIT();
        }
        if (it + 2 < NIT) CP_WAIT(1); else CP_WAIT(0);
        __syncthreads();
        if (it + 1 < NIT) qk_issue(cn, kBA[(it + 1) & 3]);
#pragma unroll
        for (int i = 0; i < 2; ++i)
#pragma unroll
            for (int j = 0; j < 8; ++j) {
                rsum[i][0] += exp2f(cc[i][j][0]) + exp2f(cc[i][j][1]);
                rsum[i][1] += exp2f(cc[i][j][2]) + exp2f(cc[i][j][3]);
            }
    };
    for (int it = 0; it < NIT; it += 2) {
        bodyA(it, cA, cB);
        bodyA(it + 1, cB, cA);
    }
#pragma unroll
    for (int i = 0; i < 2; ++i)
#pragma unroll
        for (int h = 0; h < 2; ++h) {
            float v = rsum[i][h];
            v += __shfl_xor_sync(0xffffffffu, v, 1);
            v += __shfl_xor_sync(0xffffffffu, v, 2);
            if (tg == 0) atomicAdd(&RS[wq + i * 16 + h * 8 + g], v);
        }
    __syncthreads();
    if (tid < 64) g_RS[b * SEQ + q0 + tid] = RS[tid];
}

// ================= Kernel B: attn + AV (register P) — round-13 winner =================
__global__ void __launch_bounds__(NTH, 1)
attn_fused(float* __restrict__ outp, float* __restrict__ attnp) {
    extern __shared__ __half sh[];
    const uint32_t smb = (uint32_t)__cvta_generic_to_shared(sh);

    const int tid = threadIdx.x, w = tid >> 5, lane = tid & 31;
    const int g = lane >> 2, tg = lane & 3;
    const int lr3 = lane & 7, b3 = (lane >> 3) & 1, b4 = (lane >> 4) & 1;
    const int b = blockIdx.x >> 5;
    const int q0 = (blockIdx.x & 31) << 7;
    const int wq = (w >> 1) * 32;      // 4 q-groups of 32 rows
    const int wnq = (w & 1) * 64;      // 2 n-groups of 64 cols

    const uint32_t kq_off = (uint32_t)(wnq + b4 * 8 + lr3) * 144u + (uint32_t)b3 * 16u;
    const uint32_t pa72 = (uint32_t)(b3 * 8 + lr3) * 144u + (uint32_t)b4 * 16u;
    const uint32_t va_off = (uint32_t)(wnq + b3 * 8 + lr3) * 144u + (uint32_t)b4 * 16u;

    const __half* Qh = g_QH + ((size_t)b * SEQ + q0) * HD;
    const __half* Kh = g_KH + (size_t)b * SEQ * HD;
    const __half* Vh = g_VH + (size_t)b * SEQ * HD;

    // stage a 128x64 fp16 tile via cp.async. perm!=0 applies the within-16-row
    // permutation tau so each thread's C-fragment cols become 4-contiguous.
    auto stage = [&](uint32_t hbase, const __half* gsrc, int perm) {
#pragma unroll
        for (int t = 0; t < 4; ++t) {
            int ci = tid + t * NTH;
            int row = ci >> 3, c8 = ci & 7;
            int r = row & 15;
            int srow = perm ? ((row & 112) | (r & 1) | (((r >> 3) & 1) << 1) |
                              (((r >> 1) & 3) << 2))
                            : row;
            cpa16(smb + 2u * (uint32_t)(hbase + row * KSTR) + (uint32_t)c8 * 16u,
                  gsrc + srow * HD + c8 * 8);
        }
    };

    const uint32_t kB[4] = {smb + 2u * (H_K + 0 * 9216), smb + 2u * (H_K + 1 * 9216),
                            smb + 2u * (H_K + 2 * 9216), smb + 2u * (H_K + 3 * 9216)};
    const uint32_t vB[4] = {smb + 2u * (H_V + 0 * 9216), smb + 2u * (H_V + 1 * 9216),
                            smb + 2u * (H_V + 2 * 9216), smb + 2u * (H_V + 3 * 9216)};

    // ---- prologue: Q (into V slot 0) + first K tiles ----
    stage(H_V, Qh, 0);
    CP_COMMIT();
    stage(H_K + 0 * 9216, Kh, 1);
    CP_COMMIT();
    stage(H_K + 1 * 9216, Kh + TN * HD, 1);
    CP_COMMIT();
    CP_WAIT(1);  // Q + K0 landed (K1 may fly)
    __syncthreads();

    // hoist Q fragments
    uint32_t qf[4][2][4];
#pragma unroll
    for (int kk = 0; kk < 4; ++kk)
#pragma unroll
        for (int i = 0; i < 2; ++i)
            ldsm4(qf[kk][i][0], qf[kk][i][1], qf[kk][i][2], qf[kk][i][3],
                  vB[0] + (uint32_t)(wq + i * 16) * 144u + pa72 + kk * 32u);

    // rowsums from kernel A
    float lr[2][2];
#pragma unroll
    for (int i = 0; i < 2; ++i)
#pragma unroll
        for (int h = 0; h < 2; ++h)
            lr[i][h] = -log2f(g_RS[b * SEQ + q0 + wq + i * 16 + h * 8 + g]);

    __syncthreads();  // all warps hoisted Q before V0 overwrites it
    stage(H_V + 0 * 9216, Vh, 1);
    CP_COMMIT();
    stage(H_V + 1 * 9216, Vh + TN * HD, 1);
    CP_COMMIT();
    CP_WAIT(0);
    __syncthreads();

    float c[2][8][4];
    auto qk_issue = [&](uint32_t kbuf) {
#pragma unroll
        for (int kk = 0; kk < 4; ++kk) {
#pragma unroll
            for (int j2 = 0; j2 < 8; j2 += 2) {
                uint32_t b0, b1, b2_, b3_;
                ldsm4(b0, b1, b2_, b3_, kbuf + kq_off + (uint32_t)j2 * 1152u + kk * 32u);
                if (kk == 0) {
                    mma16_z(c[0][j2], qf[0][0], b0, b1);
                    mma16_z(c[1][j2], qf[0][1], b0, b1);
                    mma16_z(c[0][j2 + 1], qf[0][0], b2_, b3_);
                    mma16_z(c[1][j2 + 1], qf[0][1], b2_, b3_);
                } else {
                    mma16(c[0][j2], qf[kk][0], b0, b1);
                    mma16(c[1][j2], qf[kk][1], b0, b1);
                    mma16(c[0][j2 + 1], qf[kk][0], b2_, b3_);
                    mma16(c[1][j2 + 1], qf[kk][1], b2_, b3_);
                }
            }
        }
    };

    float o[2][8][4] = {};
    qk_issue(kB[0]);

    for (int it = 0; it < NIT; ++it) {
        const int n0 = it * TN;
        // --- pre-barrier: stage(it+2), exp + attn STG.128, pack P into regs ---
        if (it + 2 < NIT) {
            stage(H_K + ((it + 2) & 3) * 9216, Kh + (it + 2) * TN * HD, 1);
            stage(H_V + ((it + 2) & 3) * 9216, Vh + (it + 2) * TN * HD, 1);
            CP_COMMIT();
        }
#pragma unroll
        for (int i = 0; i < 2; ++i) {
            const int row = q0 + wq + i * 16 + g;
            float* ar0 = attnp + ((size_t)b * SEQ + row) * SEQ + n0 + wnq + 4 * tg;
            float* ar1 = ar0 + (size_t)8 * SEQ;
#pragma unroll
            for (int jp = 0; jp < 4; ++jp) {
                c[i][2 * jp][0] = exp2f(c[i][2 * jp][0] + lr[i][0]);
                c[i][2 * jp][1] = exp2f(c[i][2 * jp][1] + lr[i][0]);
                c[i][2 * jp][2] = exp2f(c[i][2 * jp][2] + lr[i][1]);
                c[i][2 * jp][3] = exp2f(c[i][2 * jp][3] + lr[i][1]);
                c[i][2 * jp + 1][0] = exp2f(c[i][2 * jp + 1][0] + lr[i][0]);
                c[i][2 * jp + 1][1] = exp2f(c[i][2 * jp + 1][1] + lr[i][0]);
                c[i][2 * jp + 1][2] = exp2f(c[i][2 * jp + 1][2] + lr[i][1]);
                c[i][2 * jp + 1][3] = exp2f(c[i][2 * jp + 1][3] + lr[i][1]);
                __stcs(reinterpret_cast<float4*>(ar0 + 16 * jp),
                       make_float4(c[i][2 * jp][0], c[i][2 * jp][1],
                                   c[i][2 * jp + 1][0], c[i][2 * jp + 1][1]));
                __stcs(reinterpret_cast<float4*>(ar1 + 16 * jp),
                       make_float4(c[i][2 * jp][2], c[i][2 * jp][3],
                                   c[i][2 * jp + 1][2], c[i][2 * jp + 1][3]));
            }
        }
        uint32_t a[4][2][4];
#pragma unroll
        for (int kk = 0; kk < 4; ++kk)
#pragma unroll
            for (int i = 0; i < 2; ++i) {
                a[kk][i][0] = f2h2(c[i][2 * kk][0], c[i][2 * kk][1]);
                a[kk][i][1] = f2h2(c[i][2 * kk][2], c[i][2 * kk][3]);
                a[kk][i][2] = f2h2(c[i][2 * kk + 1][0], c[i][2 * kk + 1][1]);
                a[kk][i][3] = f2h2(c[i][2 * kk + 1][2], c[i][2 * kk + 1][3]);
            }
        if (it + 2 < NIT) CP_WAIT(1); else CP_WAIT(0);
        __syncthreads();
        // --- post-barrier: next QK first (c dead), then AV fills its latency ---
        if (it + 1 < NIT) qk_issue(kB[(it + 1) & 3]);
        const uint32_t vb = vB[it & 3];
#pragma unroll
        for (int kk = 0; kk < 4; ++kk) {
#pragma unroll
            for (int j = 0; j < 4; ++j) {
                uint32_t b0, b1, b2_, b3_;
                ldsm4t(b0, b1, b2_, b3_, vb + va_off + (uint32_t)kk * 2304u + j * 32u);
                mma16(o[0][2 * j], a[kk][0], b0, b1);
                mma16(o[1][2 * j], a[kk][1], b0, b1);
                mma16(o[0][2 * j + 1], a[kk][0], b2_, b3_);
                mma16(o[1][2 * j + 1], a[kk][1], b2_, b3_);
            }
        }
    }

    // ---- epilogue: reduce partial O across the 2 n-groups, write out ----
    float* FS = reinterpret_cast<float*>(sh);  // reuse K ring
    const int qg = w >> 1;
    __syncthreads();
    if (w & 1) {
#pragma unroll
        for (int i = 0; i < 2; ++i)
#pragma unroll
            for (int j = 0; j < 8; ++j) {
                const int col = j * 8 + 2 * tg;
                *reinterpret_cast<float2*>(&FS[qg * 2048 + (i * 16 + g) * 64 + col]) =
                    make_float2(o[i][j][0], o[i][j][1]);
                *reinterpret_cast<float2*>(&FS[qg * 2048 + (i * 16 + 8 + g) * 64 + col]) =
                    make_float2(o[i][j][2], o[i][j][3]);
            }
    }
    __syncthreads();
    if (!(w & 1)) {
#pragma unroll
        for (int i = 0; i < 2; ++i) {
            const int row = q0 + wq + i * 16 + g;
            float* orow = outp + ((size_t)b * SEQ + row) * HD;
#pragma unroll
            for (int j = 0; j < 8; ++j) {
                const int col = j * 8 + 2 * tg;
                float2 p0 =
                    *reinterpret_cast<float2*>(&FS[qg * 2048 + (i * 16 + g) * 64 + col]);
                float2 p1 = *reinterpret_cast<float2*>(
                    &FS[qg * 2048 + (i * 16 + 8 + g) * 64 + col]);
                *reinterpret_cast<float2*>(orow + col) =
                    make_float2(o[i][j][0] + p0.x, o[i][j][1] + p0.y);
                *reinterpret_cast<float2*>(orow + 8 * HD + col) =
                    make_float2(o[i][j][2] + p1.x, o[i][j][3] + p1.y);
            }
        }
    }
}

extern "C" void kernel_launch(void* const* d_in, const int* in_sizes, int n_in,
                              void* d_out, int out_size) {
    const float* q = (const float*)d_in[0];
    const float* k = (const float*)d_in[1];
    const float* v = (const float*)d_in[2];
    float* outp = (float*)d_out;
    float* attnp = outp + (size_t)NBATCH * SEQ * HD;

    cvt_kernel<<<NBATCH * SEQ * HD / (256 * 4), 256>>>(q, k, v);

    cudaFuncSetAttribute(attn_sums_k, cudaFuncAttributeMaxDynamicSharedMemorySize,
                         SMEMA_BYTES);
    cudaFuncSetAttribute(attn_fused, cudaFuncAttributeMaxDynamicSharedMemorySize,
                         SMEMB_BYTES);

    attn_sums_k<<<NBATCH * 64, 128, SMEMA_BYTES>>>();
    attn_fused<<<NBATCH * 32, NTH, SMEMB_BYTES>>>(outp, attnp);
}

// round 16
// speedup vs baseline: 1.0929x; 1.0631x over previous
#include <cuda_runtime.h>
#include <cuda_fp16.h>
#include <cstdint>

#define SEQ 4096
#define HD 64
#define NBATCH 4
#define TN 128
#define NIT 32
#define NTH 256
#define CEXP 0.18033688011112042f  // log2(e)/temperature(8) — folded into Q

#define KSTR 72    // K/V tile row stride in halves (144B)

// ---- phase B smem (half offsets): ring-4 K + ring-4 V ----
#define H_K 0                // 4 rings of 128*72 = 9216
#define H_V 36864            // 4 rings of 9216 (slot 0 doubles as Q staging)
#define H_TOT 73728
#define SMEMB_BYTES (H_TOT * 2 + 128 * 4)

// ---- phase A smem (half offsets) ----
#define HA_Q 0               // 64*72 = 4608 halves
#define HA_K 4608            // 4 rings of 9216
#define HA_TOT 41472
#define SMEMA_BYTES (HA_TOT * 2 + 64 * 4)

__device__ __half g_QH[NBATCH * SEQ * HD];
__device__ __half g_KH[NBATCH * SEQ * HD];
__device__ __half g_VH[NBATCH * SEQ * HD];
__device__ float g_RS[NBATCH * SEQ];

__device__ __forceinline__ uint32_t f2h2(float x, float y) {
    __half2 h = __floats2half2_rn(x, y);
    return *reinterpret_cast<uint32_t*>(&h);
}
__device__ __forceinline__ void ldsm4(uint32_t& r0, uint32_t& r1, uint32_t& r2,
                                      uint32_t& r3, uint32_t addr) {
    asm volatile("ldmatrix.sync.aligned.m8n8.x4.shared.b16 {%0,%1,%2,%3}, [%4];"
                 : "=r"(r0), "=r"(r1), "=r"(r2), "=r"(r3) : "r"(addr));
}
__device__ __forceinline__ void ldsm4t(uint32_t& r0, uint32_t& r1, uint32_t& r2,
                                       uint32_t& r3, uint32_t addr) {
    asm volatile("ldmatrix.sync.aligned.m8n8.x4.trans.shared.b16 {%0,%1,%2,%3}, [%4];"
                 : "=r"(r0), "=r"(r1), "=r"(r2), "=r"(r3) : "r"(addr));
}
__device__ __forceinline__ void mma16(float c[4], const uint32_t a[4], uint32_t b0,
                                      uint32_t b1) {
    asm volatile(
        "mma.sync.aligned.m16n8k16.row.col.f32.f16.f16.f32 "
        "{%0,%1,%2,%3}, {%4,%5,%6,%7}, {%8,%9}, {%0,%1,%2,%3};\n"
        : "+f"(c[0]), "+f"(c[1]), "+f"(c[2]), "+f"(c[3])
        : "r"(a[0]), "r"(a[1]), "r"(a[2]), "r"(a[3]), "r"(b0), "r"(b1));
}
__device__ __forceinline__ void mma16_z(float d[4], const uint32_t a[4], uint32_t b0,
                                        uint32_t b1) {
    asm volatile(
        "mma.sync.aligned.m16n8k16.row.col.f32.f16.f16.f32 "
        "{%0,%1,%2,%3}, {%4,%5,%6,%7}, {%8,%9}, {%10,%10,%10,%10};\n"
        : "=f"(d[0]), "=f"(d[1]), "=f"(d[2]), "=f"(d[3])
        : "r"(a[0]), "r"(a[1]), "r"(a[2]), "r"(a[3]), "r"(b0), "r"(b1), "f"(0.f));
}
__device__ __forceinline__ void cpa16(uint32_t dst, const __half* src) {
    asm volatile("cp.async.cg.shared.global [%0], [%1], 16;" ::"r"(dst), "l"(src));
}
#define CP_COMMIT() asm volatile("cp.async.commit_group;" ::: "memory")
#define CP_WAIT(n) asm volatile("cp.async.wait_group %0;" ::"n"(n) : "memory")

// ---- pre-pass: fp32 -> fp16; Q pre-scaled by log2(e)/temperature ----
__global__ void __launch_bounds__(256) cvt_kernel(const float* __restrict__ q,
                                                  const float* __restrict__ k,
                                                  const float* __restrict__ v) {
    int i = (blockIdx.x * 256 + threadIdx.x) * 4;
    float4 a = *reinterpret_cast<const float4*>(q + i);
    float4 bk = *reinterpret_cast<const float4*>(k + i);
    float4 c = *reinterpret_cast<const float4*>(v + i);
    *reinterpret_cast<uint2*>(&g_QH[i]) =
        make_uint2(f2h2(a.x * CEXP, a.y * CEXP), f2h2(a.z * CEXP, a.w * CEXP));
    *reinterpret_cast<uint2*>(&g_KH[i]) = make_uint2(f2h2(bk.x, bk.y), f2h2(bk.z, bk.w));
    *reinterpret_cast<uint2*>(&g_VH[i]) = make_uint2(f2h2(c.x, c.y), f2h2(c.z, c.w));
}

// ===== Kernel A: rowsums of exp (round-13 form: 2 CTAs/SM, single score buffer) =====
__global__ void __launch_bounds__(128, 2) attn_sums_k() {
    extern __shared__ __half sh[];
    float* RS = reinterpret_cast<float*>(sh + HA_TOT);
    const uint32_t smb = (uint32_t)__cvta_generic_to_shared(sh);

    const int tid = threadIdx.x, w = tid >> 5, lane = tid & 31;
    const int g = lane >> 2, tg = lane & 3;
    const int lr3 = lane & 7, b3 = (lane >> 3) & 1, b4 = (lane >> 4) & 1;
    const int b = blockIdx.x >> 6;
    const int q0 = (blockIdx.x & 63) << 6;
    const int wq = (w >> 1) * 32;
    const int wnq = (w & 1) * 64;

    const uint32_t kq_off = (uint32_t)(wnq + b4 * 8 + lr3) * 144u + (uint32_t)b3 * 16u;
    const uint32_t pa72 = (uint32_t)(b3 * 8 + lr3) * 144u + (uint32_t)b4 * 16u;

    const __half* Qh = g_QH + ((size_t)b * SEQ + q0) * HD;
    const __half* Kh = g_KH + (size_t)b * SEQ * HD;

    if (tid < 64) RS[tid] = 0.f;

    auto stageK = [&](int slot, const __half* src) {
#pragma unroll
        for (int t = 0; t < 8; ++t) {
            int ci = tid + t * 128;
            int row = ci >> 3, c8 = ci & 7;
            cpa16(smb + 2u * (uint32_t)(HA_K + slot * 9216 + row * KSTR) +
                      (uint32_t)c8 * 16u,
                  src + row * HD + c8 * 8);
        }
    };
#pragma unroll
    for (int t = 0; t < 4; ++t) {
        int ci = tid + t * 128;
        int row = ci >> 3, c8 = ci & 7;
        cpa16(smb + 2u * (uint32_t)(HA_Q + row * KSTR) + (uint32_t)c8 * 16u,
              Qh + row * HD + c8 * 8);
    }
    CP_COMMIT();
    stageK(0, Kh);
    CP_COMMIT();
    stageK(1, Kh + TN * HD);
    CP_COMMIT();
    CP_WAIT(0);
    __syncthreads();

    uint32_t qf[4][2][4];
#pragma unroll
    for (int kk = 0; kk < 4; ++kk)
#pragma unroll
        for (int i = 0; i < 2; ++i)
            ldsm4(qf[kk][i][0], qf[kk][i][1], qf[kk][i][2], qf[kk][i][3],
                  smb + 2u * HA_Q + (uint32_t)(wq + i * 16) * 144u + pa72 + kk * 32u);

    const uint32_t kBA[4] = {
        smb + 2u * (HA_K + 0 * 9216), smb + 2u * (HA_K + 1 * 9216),
        smb + 2u * (HA_K + 2 * 9216), smb + 2u * (HA_K + 3 * 9216)};

    float c[2][8][4];
    auto qk_issue = [&](uint32_t kbuf) {
#pragma unroll
        for (int kk = 0; kk < 4; ++kk) {
#pragma unroll
            for (int j2 = 0; j2 < 8; j2 += 2) {
                uint32_t b0, b1, b2_, b3_;
                ldsm4(b0, b1, b2_, b3_, kbuf + kq_off + (uint32_t)j2 * 1152u + kk * 32u);
                if (kk == 0) {
                    mma16_z(c[0][j2], qf[0][0], b0, b1);
                    mma16_z(c[1][j2], qf[0][1], b0, b1);
                    mma16_z(c[0][j2 + 1], qf[0][0], b2_, b3_);
                    mma16_z(c[1][j2 + 1], qf[0][1], b2_, b3_);
                } else {
                    mma16(c[0][j2], qf[kk][0], b0, b1);
                    mma16(c[1][j2], qf[kk][1], b0, b1);
                    mma16(c[0][j2 + 1], qf[kk][0], b2_, b3_);
                    mma16(c[1][j2 + 1], qf[kk][1], b2_, b3_);
                }
            }
        }
    };

    float rsum[2][2] = {{0.f, 0.f}, {0.f, 0.f}};
    qk_issue(kBA[0]);
    for (int it = 0; it < NIT; ++it) {
        if (it + 2 < NIT) {
            stageK((it + 2) & 3, Kh + (it + 2) * TN * HD);
            CP_COMMIT();
        }
#pragma unroll
        for (int i = 0; i < 2; ++i)
#pragma unroll
            for (int j = 0; j < 8; ++j) {
                rsum[i][0] += exp2f(c[i][j][0]) + exp2f(c[i][j][1]);
                rsum[i][1] += exp2f(c[i][j][2]) + exp2f(c[i][j][3]);
            }
        if (it + 2 < NIT) CP_WAIT(1); else CP_WAIT(0);
        __syncthreads();
        if (it + 1 < NIT) qk_issue(kBA[(it + 1) & 3]);
    }
#pragma unroll
    for (int i = 0; i < 2; ++i)
#pragma unroll
        for (int h = 0; h < 2; ++h) {
            float v = rsum[i][h];
            v += __shfl_xor_sync(0xffffffffu, v, 1);
            v += __shfl_xor_sync(0xffffffffu, v, 2);
            if (tg == 0) atomicAdd(&RS[wq + i * 16 + h * 8 + g], v);
        }
    __syncthreads();
    if (tid < 64) g_RS[b * SEQ + q0 + tid] = RS[tid];
}

// ===== Kernel B: attn + AV (register P) — round-13 + split AV =====
__global__ void __launch_bounds__(NTH, 1)
attn_fused(float* __restrict__ outp, float* __restrict__ attnp) {
    extern __shared__ __half sh[];
    const uint32_t smb = (uint32_t)__cvta_generic_to_shared(sh);

    const int tid = threadIdx.x, w = tid >> 5, lane = tid & 31;
    const int g = lane >> 2, tg = lane & 3;
    const int lr3 = lane & 7, b3 = (lane >> 3) & 1, b4 = (lane >> 4) & 1;
    const int b = blockIdx.x >> 5;
    const int q0 = (blockIdx.x & 31) << 7;
    const int wq = (w >> 1) * 32;      // 4 q-groups of 32 rows
    const int wnq = (w & 1) * 64;      // 2 n-groups of 64 cols

    const uint32_t kq_off = (uint32_t)(wnq + b4 * 8 + lr3) * 144u + (uint32_t)b3 * 16u;
    const uint32_t pa72 = (uint32_t)(b3 * 8 + lr3) * 144u + (uint32_t)b4 * 16u;
    const uint32_t va_off = (uint32_t)(wnq + b3 * 8 + lr3) * 144u + (uint32_t)b4 * 16u;

    const __half* Qh = g_QH + ((size_t)b * SEQ + q0) * HD;
    const __half* Kh = g_KH + (size_t)b * SEQ * HD;
    const __half* Vh = g_VH + (size_t)b * SEQ * HD;

    // stage a 128x64 fp16 tile via cp.async; perm applies tau (round-12 layout)
    auto stage = [&](uint32_t hbase, const __half* gsrc, int perm) {
#pragma unroll
        for (int t = 0; t < 4; ++t) {
            int ci = tid + t * NTH;
            int row = ci >> 3, c8 = ci & 7;
            int r = row & 15;
            int srow = perm ? ((row & 112) | (r & 1) | (((r >> 3) & 1) << 1) |
                              (((r >> 1) & 3) << 2))
                            : row;
            cpa16(smb + 2u * (uint32_t)(hbase + row * KSTR) + (uint32_t)c8 * 16u,
                  gsrc + srow * HD + c8 * 8);
        }
    };

    const uint32_t kB[4] = {smb + 2u * (H_K + 0 * 9216), smb + 2u * (H_K + 1 * 9216),
                            smb + 2u * (H_K + 2 * 9216), smb + 2u * (H_K + 3 * 9216)};
    const uint32_t vB[4] = {smb + 2u * (H_V + 0 * 9216), smb + 2u * (H_V + 1 * 9216),
                            smb + 2u * (H_V + 2 * 9216), smb + 2u * (H_V + 3 * 9216)};

    // ---- prologue: Q (into V slot 0) + first K tiles ----
    stage(H_V, Qh, 0);
    CP_COMMIT();
    stage(H_K + 0 * 9216, Kh, 1);
    CP_COMMIT();
    stage(H_K + 1 * 9216, Kh + TN * HD, 1);
    CP_COMMIT();
    CP_WAIT(1);  // Q + K0 landed (K1 may fly)
    __syncthreads();

    // hoist Q fragments
    uint32_t qf[4][2][4];
#pragma unroll
    for (int kk = 0; kk < 4; ++kk)
#pragma unroll
        for (int i = 0; i < 2; ++i)
            ldsm4(qf[kk][i][0], qf[kk][i][1], qf[kk][i][2], qf[kk][i][3],
                  vB[0] + (uint32_t)(wq + i * 16) * 144u + pa72 + kk * 32u);

    // rowsums from kernel A
    float lr[2][2];
#pragma unroll
    for (int i = 0; i < 2; ++i)
#pragma unroll
        for (int h = 0; h < 2; ++h)
            lr[i][h] = -log2f(g_RS[b * SEQ + q0 + wq + i * 16 + h * 8 + g]);

    __syncthreads();  // all warps hoisted Q before V0 overwrites it
    stage(H_V + 0 * 9216, Vh, 1);
    CP_COMMIT();
    stage(H_V + 1 * 9216, Vh + TN * HD, 1);
    CP_COMMIT();
    CP_WAIT(0);
    __syncthreads();

    float c[2][8][4];
    auto qk_issue = [&](uint32_t kbuf) {
#pragma unroll
        for (int kk = 0; kk < 4; ++kk) {
#pragma unroll
            for (int j2 = 0; j2 < 8; j2 += 2) {
                uint32_t b0, b1, b2_, b3_;
                ldsm4(b0, b1, b2_, b3_, kbuf + kq_off + (uint32_t)j2 * 1152u + kk * 32u);
                if (kk == 0) {
                    mma16_z(c[0][j2], qf[0][0], b0, b1);
                    mma16_z(c[1][j2], qf[0][1], b0, b1);
                    mma16_z(c[0][j2 + 1], qf[0][0], b2_, b3_);
                    mma16_z(c[1][j2 + 1], qf[0][1], b2_, b3_);
                } else {
                    mma16(c[0][j2], qf[kk][0], b0, b1);
                    mma16(c[1][j2], qf[kk][1], b0, b1);
                    mma16(c[0][j2 + 1], qf[kk][0], b2_, b3_);
                    mma16(c[1][j2 + 1], qf[kk][1], b2_, b3_);
                }
            }
        }
    };

    float o[2][8][4] = {};
    qk_issue(kB[0]);

    uint32_t a[4][2][4];
    // AV half: kk in [klo, khi) — preserves o accumulation chain order
    auto av_half = [&](uint32_t vb, int klo, int khi) {
        for (int kk = klo; kk < khi; ++kk) {
#pragma unroll
            for (int j = 0; j < 4; ++j) {
                uint32_t b0, b1, b2_, b3_;
                ldsm4t(b0, b1, b2_, b3_, vb + va_off + (uint32_t)kk * 2304u + j * 32u);
                mma16(o[0][2 * j], a[kk][0], b0, b1);
                mma16(o[1][2 * j], a[kk][1], b0, b1);
                mma16(o[0][2 * j + 1], a[kk][0], b2_, b3_);
                mma16(o[1][2 * j + 1], a[kk][1], b2_, b3_);
            }
        }
    };

    for (int it = 0; it < NIT; ++it) {
        const int n0 = it * TN;
        const uint32_t vb = vB[it & 3];
        // --- pre-barrier: stage(it+2), exp + attn STG.128, pack P, AV half 1 ---
        if (it + 2 < NIT) {
            stage(H_K + ((it + 2) & 3) * 9216, Kh + (it + 2) * TN * HD, 1);
            stage(H_V + ((it + 2) & 3) * 9216, Vh + (it + 2) * TN * HD, 1);
            CP_COMMIT();
        }
#pragma unroll
        for (int i = 0; i < 2; ++i) {
            const int row = q0 + wq + i * 16 + g;
            float* ar0 = attnp + ((size_t)b * SEQ + row) * SEQ + n0 + wnq + 4 * tg;
            float* ar1 = ar0 + (size_t)8 * SEQ;
#pragma unroll
            for (int jp = 0; jp < 4; ++jp) {
                c[i][2 * jp][0] = exp2f(c[i][2 * jp][0] + lr[i][0]);
                c[i][2 * jp][1] = exp2f(c[i][2 * jp][1] + lr[i][0]);
                c[i][2 * jp][2] = exp2f(c[i][2 * jp][2] + lr[i][1]);
                c[i][2 * jp][3] = exp2f(c[i][2 * jp][3] + lr[i][1]);
                c[i][2 * jp + 1][0] = exp2f(c[i][2 * jp + 1][0] + lr[i][0]);
                c[i][2 * jp + 1][1] = exp2f(c[i][2 * jp + 1][1] + lr[i][0]);
                c[i][2 * jp + 1][2] = exp2f(c[i][2 * jp + 1][2] + lr[i][1]);
                c[i][2 * jp + 1][3] = exp2f(c[i][2 * jp + 1][3] + lr[i][1]);
                __stcs(reinterpret_cast<float4*>(ar0 + 16 * jp),
                       make_float4(c[i][2 * jp][0], c[i][2 * jp][1],
                                   c[i][2 * jp + 1][0], c[i][2 * jp + 1][1]));
                __stcs(reinterpret_cast<float4*>(ar1 + 16 * jp),
                       make_float4(c[i][2 * jp][2], c[i][2 * jp][3],
                                   c[i][2 * jp + 1][2], c[i][2 * jp + 1][3]));
            }
        }
#pragma unroll
        for (int kk = 0; kk < 4; ++kk)
#pragma unroll
            for (int i = 0; i < 2; ++i) {
                a[kk][i][0] = f2h2(c[i][2 * kk][0], c[i][2 * kk][1]);
                a[kk][i][1] = f2h2(c[i][2 * kk][2], c[i][2 * kk][3]);
                a[kk][i][2] = f2h2(c[i][2 * kk + 1][0], c[i][2 * kk + 1][1]);
                a[kk][i][3] = f2h2(c[i][2 * kk + 1][2], c[i][2 * kk + 1][3]);
            }
        av_half(vb, 0, 2);  // AV first half fills the pre-barrier tensor gap
        if (it + 2 < NIT) CP_WAIT(1); else CP_WAIT(0);
        __syncthreads();
        // --- post-barrier: next QK first (c dead), AV second half fills latency ---
        if (it + 1 < NIT) qk_issue(kB[(it + 1) & 3]);
        av_half(vb, 2, 4);
    }

    // ---- epilogue: reduce partial O across the 2 n-groups, write out ----
    float* FS = reinterpret_cast<float*>(sh);  // reuse K ring
    const int qg = w >> 1;
    __syncthreads();
    if (w & 1) {
#pragma unroll
        for (int i = 0; i < 2; ++i)
#pragma unroll
            for (int j = 0; j < 8; ++j) {
                const int col = j * 8 + 2 * tg;
                *reinterpret_cast<float2*>(&FS[qg * 2048 + (i * 16 + g) * 64 + col]) =
                    make_float2(o[i][j][0], o[i][j][1]);
                *reinterpret_cast<float2*>(&FS[qg * 2048 + (i * 16 + 8 + g) * 64 + col]) =
                    make_float2(o[i][j][2], o[i][j][3]);
            }
    }
    __syncthreads();
    if (!(w & 1)) {
#pragma unroll
        for (int i = 0; i < 2; ++i) {
            const int row = q0 + wq + i * 16 + g;
            float* orow = outp + ((size_t)b * SEQ + row) * HD;
#pragma unroll
            for (int j = 0; j < 8; ++j) {
                const int col = j * 8 + 2 * tg;
                float2 p0 =
                    *reinterpret_cast<float2*>(&FS[qg * 2048 + (i * 16 + g) * 64 + col]);
                float2 p1 = *reinterpret_cast<float2*>(
                    &FS[qg * 2048 + (i * 16 + 8 + g) * 64 + col]);
                *reinterpret_cast<float2*>(orow + col) =
                    make_float2(o[i][j][0] + p0.x, o[i][j][1] + p0.y);
                *reinterpret_cast<float2*>(orow + 8 * HD + col) =
                    make_float2(o[i][j][2] + p1.x, o[i][j][3] + p1.y);
            }
        }
    }
}

extern "C" void kernel_launch(void* const* d_in, const int* in_sizes, int n_in,
                              void* d_out, int out_size) {
    const float* q = (const float*)d_in[0];
    const float* k = (const float*)d_in[1];
    const float* v = (const float*)d_in[2];
    float* outp = (float*)d_out;
    float* attnp = outp + (size_t)NBATCH * SEQ * HD;

    cvt_kernel<<<NBATCH * SEQ * HD / (256 * 4), 256>>>(q, k, v);

    cudaFuncSetAttribute(attn_sums_k, cudaFuncAttributeMaxDynamicSharedMemorySize,
                         SMEMA_BYTES);
    cudaFuncSetAttribute(attn_fused, cudaFuncAttributeMaxDynamicSharedMemorySize,
                         SMEMB_BYTES);

    attn_sums_k<<<NBATCH * 64, 128, SMEMA_BYTES>>>();
    attn_fused<<<NBATCH * 32, NTH, SMEMB_BYTES>>>(outp, attnp);
}

// round 17
// speedup vs baseline: 1.1309x; 1.0348x over previous
#include <cuda_runtime.h>
#include <cuda_fp16.h>
#include <cstdint>

#define SEQ 4096
#define HD 64
#define NBATCH 4
#define TN 128
#define NIT 32
#define NTH 256
#define CEXP 0.18033688011112042f  // log2(e)/temperature(8) — folded into Q

#define KSTR 72    // K/V tile row stride in halves (144B)

// ---- phase B smem (half offsets): ring-4 K + ring-4 V ----
#define H_K 0                // 4 rings of 128*72 = 9216
#define H_V 36864            // 4 rings of 9216 (slot 0 doubles as Q staging)
#define H_TOT 73728
#define SMEMB_BYTES (H_TOT * 2 + 128 * 4)

// ---- phase A smem (half offsets) ----
#define HA_Q 0               // 64*72 = 4608 halves
#define HA_K 4608            // 4 rings of 9216
#define HA_TOT 41472
#define SMEMA_BYTES (HA_TOT * 2 + 64 * 4)

__device__ __half g_QH[NBATCH * SEQ * HD];
__device__ __half g_KH[NBATCH * SEQ * HD];
__device__ __half g_VH[NBATCH * SEQ * HD];
__device__ float g_RS[NBATCH * SEQ];

__device__ __forceinline__ uint32_t f2h2(float x, float y) {
    __half2 h = __floats2half2_rn(x, y);
    return *reinterpret_cast<uint32_t*>(&h);
}
__device__ __forceinline__ void ldsm4(uint32_t& r0, uint32_t& r1, uint32_t& r2,
                                      uint32_t& r3, uint32_t addr) {
    asm volatile("ldmatrix.sync.aligned.m8n8.x4.shared.b16 {%0,%1,%2,%3}, [%4];"
                 : "=r"(r0), "=r"(r1), "=r"(r2), "=r"(r3) : "r"(addr));
}
__device__ __forceinline__ void ldsm4t(uint32_t& r0, uint32_t& r1, uint32_t& r2,
                                       uint32_t& r3, uint32_t addr) {
    asm volatile("ldmatrix.sync.aligned.m8n8.x4.trans.shared.b16 {%0,%1,%2,%3}, [%4];"
                 : "=r"(r0), "=r"(r1), "=r"(r2), "=r"(r3) : "r"(addr));
}
__device__ __forceinline__ void mma16(float c[4], const uint32_t a[4], uint32_t b0,
                                      uint32_t b1) {
    asm volatile(
        "mma.sync.aligned.m16n8k16.row.col.f32.f16.f16.f32 "
        "{%0,%1,%2,%3}, {%4,%5,%6,%7}, {%8,%9}, {%0,%1,%2,%3};\n"
        : "+f"(c[0]), "+f"(c[1]), "+f"(c[2]), "+f"(c[3])
        : "r"(a[0]), "r"(a[1]), "r"(a[2]), "r"(a[3]), "r"(b0), "r"(b1));
}
__device__ __forceinline__ void mma16_z(float d[4], const uint32_t a[4], uint32_t b0,
                                        uint32_t b1) {
    asm volatile(
        "mma.sync.aligned.m16n8k16.row.col.f32.f16.f16.f32 "
        "{%0,%1,%2,%3}, {%4,%5,%6,%7}, {%8,%9}, {%10,%10,%10,%10};\n"
        : "=f"(d[0]), "=f"(d[1]), "=f"(d[2]), "=f"(d[3])
        : "r"(a[0]), "r"(a[1]), "r"(a[2]), "r"(a[3]), "r"(b0), "r"(b1), "f"(0.f));
}
__device__ __forceinline__ void cpa16(uint32_t dst, const __half* src) {
    asm volatile("cp.async.cg.shared.global [%0], [%1], 16;" ::"r"(dst), "l"(src));
}
#define CP_COMMIT() asm volatile("cp.async.commit_group;" ::: "memory")
#define CP_WAIT(n) asm volatile("cp.async.wait_group %0;" ::"n"(n) : "memory")

// ---- pre-pass: fp32 -> fp16; Q pre-scaled by log2(e)/temperature ----
__global__ void __launch_bounds__(256) cvt_kernel(const float* __restrict__ q,
                                                  const float* __restrict__ k,
                                                  const float* __restrict__ v) {
    int i = (blockIdx.x * 256 + threadIdx.x) * 4;
    float4 a = *reinterpret_cast<const float4*>(q + i);
    float4 bk = *reinterpret_cast<const float4*>(k + i);
    float4 c = *reinterpret_cast<const float4*>(v + i);
    *reinterpret_cast<uint2*>(&g_QH[i]) =
        make_uint2(f2h2(a.x * CEXP, a.y * CEXP), f2h2(a.z * CEXP, a.w * CEXP));
    *reinterpret_cast<uint2*>(&g_KH[i]) = make_uint2(f2h2(bk.x, bk.y), f2h2(bk.z, bk.w));
    *reinterpret_cast<uint2*>(&g_VH[i]) = make_uint2(f2h2(c.x, c.y), f2h2(c.z, c.w));
}

// ===== Kernel A: rowsums of exp (2 CTAs/SM, single score buffer) =====
__global__ void __launch_bounds__(128, 2) attn_sums_k() {
    extern __shared__ __half sh[];
    float* RS = reinterpret_cast<float*>(sh + HA_TOT);
    const uint32_t smb = (uint32_t)__cvta_generic_to_shared(sh);

    const int tid = threadIdx.x, w = tid >> 5, lane = tid & 31;
    const int g = lane >> 2, tg = lane & 3;
    const int lr3 = lane & 7, b3 = (lane >> 3) & 1, b4 = (lane >> 4) & 1;
    const int b = blockIdx.x >> 6;
    const int q0 = (blockIdx.x & 63) << 6;
    const int wq = (w >> 1) * 32;
    const int wnq = (w & 1) * 64;

    const uint32_t kq_off = (uint32_t)(wnq + b4 * 8 + lr3) * 144u + (uint32_t)b3 * 16u;
    const uint32_t pa72 = (uint32_t)(b3 * 8 + lr3) * 144u + (uint32_t)b4 * 16u;

    const __half* Qh = g_QH + ((size_t)b * SEQ + q0) * HD;
    const __half* Kh = g_KH + (size_t)b * SEQ * HD;

    if (tid < 64) RS[tid] = 0.f;

    auto stageK = [&](int slot, const __half* src) {
#pragma unroll
        for (int t = 0; t < 8; ++t) {
            int ci = tid + t * 128;
            int row = ci >> 3, c8 = ci & 7;
            cpa16(smb + 2u * (uint32_t)(HA_K + slot * 9216 + row * KSTR) +
                      (uint32_t)c8 * 16u,
                  src + row * HD + c8 * 8);
        }
    };
#pragma unroll
    for (int t = 0; t < 4; ++t) {
        int ci = tid + t * 128;
        int row = ci >> 3, c8 = ci & 7;
        cpa16(smb + 2u * (uint32_t)(HA_Q + row * KSTR) + (uint32_t)c8 * 16u,
              Qh + row * HD + c8 * 8);
    }
    CP_COMMIT();
    stageK(0, Kh);
    CP_COMMIT();
    stageK(1, Kh + TN * HD);
    CP_COMMIT();
    CP_WAIT(0);
    __syncthreads();

    uint32_t qf[4][2][4];
#pragma unroll
    for (int kk = 0; kk < 4; ++kk)
#pragma unroll
        for (int i = 0; i < 2; ++i)
            ldsm4(qf[kk][i][0], qf[kk][i][1], qf[kk][i][2], qf[kk][i][3],
                  smb + 2u * HA_Q + (uint32_t)(wq + i * 16) * 144u + pa72 + kk * 32u);

    const uint32_t kBA[4] = {
        smb + 2u * (HA_K + 0 * 9216), smb + 2u * (HA_K + 1 * 9216),
        smb + 2u * (HA_K + 2 * 9216), smb + 2u * (HA_K + 3 * 9216)};

    float c[2][8][4];
    auto qk_issue = [&](uint32_t kbuf) {
#pragma unroll
        for (int kk = 0; kk < 4; ++kk) {
#pragma unroll
            for (int j2 = 0; j2 < 8; j2 += 2) {
                uint32_t b0, b1, b2_, b3_;
                ldsm4(b0, b1, b2_, b3_, kbuf + kq_off + (uint32_t)j2 * 1152u + kk * 32u);
                if (kk == 0) {
                    mma16_z(c[0][j2], qf[0][0], b0, b1);
                    mma16_z(c[1][j2], qf[0][1], b0, b1);
                    mma16_z(c[0][j2 + 1], qf[0][0], b2_, b3_);
                    mma16_z(c[1][j2 + 1], qf[0][1], b2_, b3_);
                } else {
                    mma16(c[0][j2], qf[kk][0], b0, b1);
                    mma16(c[1][j2], qf[kk][1], b0, b1);
                    mma16(c[0][j2 + 1], qf[kk][0], b2_, b3_);
                    mma16(c[1][j2 + 1], qf[kk][1], b2_, b3_);
                }
            }
        }
    };

    float rsum[2][2] = {{0.f, 0.f}, {0.f, 0.f}};
    qk_issue(kBA[0]);
    for (int it = 0; it < NIT; ++it) {
        if (it + 2 < NIT) {
            stageK((it + 2) & 3, Kh + (it + 2) * TN * HD);
            CP_COMMIT();
        }
#pragma unroll
        for (int i = 0; i < 2; ++i)
#pragma unroll
            for (int j = 0; j < 8; ++j) {
                rsum[i][0] += exp2f(c[i][j][0]) + exp2f(c[i][j][1]);
                rsum[i][1] += exp2f(c[i][j][2]) + exp2f(c[i][j][3]);
            }
        if (it + 2 < NIT) CP_WAIT(1); else CP_WAIT(0);
        __syncthreads();
        if (it + 1 < NIT) qk_issue(kBA[(it + 1) & 3]);
    }
#pragma unroll
    for (int i = 0; i < 2; ++i)
#pragma unroll
        for (int h = 0; h < 2; ++h) {
            float v = rsum[i][h];
            v += __shfl_xor_sync(0xffffffffu, v, 1);
            v += __shfl_xor_sync(0xffffffffu, v, 2);
            if (tg == 0) atomicAdd(&RS[wq + i * 16 + h * 8 + g], v);
        }
    __syncthreads();
    if (tid < 64) g_RS[b * SEQ + q0 + tid] = RS[tid];
}

// ===== Kernel B: attn + AV — fine-grained exp/AV interleave =====
__global__ void __launch_bounds__(NTH, 1)
attn_fused(float* __restrict__ outp, float* __restrict__ attnp) {
    extern __shared__ __half sh[];
    const uint32_t smb = (uint32_t)__cvta_generic_to_shared(sh);

    const int tid = threadIdx.x, w = tid >> 5, lane = tid & 31;
    const int g = lane >> 2, tg = lane & 3;
    const int lr3 = lane & 7, b3 = (lane >> 3) & 1, b4 = (lane >> 4) & 1;
    const int b = blockIdx.x >> 5;
    const int q0 = (blockIdx.x & 31) << 7;
    const int wq = (w >> 1) * 32;      // 4 q-groups of 32 rows
    const int wnq = (w & 1) * 64;      // 2 n-groups of 64 cols

    const uint32_t kq_off = (uint32_t)(wnq + b4 * 8 + lr3) * 144u + (uint32_t)b3 * 16u;
    const uint32_t pa72 = (uint32_t)(b3 * 8 + lr3) * 144u + (uint32_t)b4 * 16u;
    const uint32_t va_off = (uint32_t)(wnq + b3 * 8 + lr3) * 144u + (uint32_t)b4 * 16u;

    const __half* Qh = g_QH + ((size_t)b * SEQ + q0) * HD;
    const __half* Kh = g_KH + (size_t)b * SEQ * HD;
    const __half* Vh = g_VH + (size_t)b * SEQ * HD;

    // stage a 128x64 fp16 tile via cp.async; perm applies tau (round-12 layout)
    auto stage = [&](uint32_t hbase, const __half* gsrc, int perm) {
#pragma unroll
        for (int t = 0; t < 4; ++t) {
            int ci = tid + t * NTH;
            int row = ci >> 3, c8 = ci & 7;
            int r = row & 15;
            int srow = perm ? ((row & 112) | (r & 1) | (((r >> 3) & 1) << 1) |
                              (((r >> 1) & 3) << 2))
                            : row;
            cpa16(smb + 2u * (uint32_t)(hbase + row * KSTR) + (uint32_t)c8 * 16u,
                  gsrc + srow * HD + c8 * 8);
        }
    };

    const uint32_t kB[4] = {smb + 2u * (H_K + 0 * 9216), smb + 2u * (H_K + 1 * 9216),
                            smb + 2u * (H_K + 2 * 9216), smb + 2u * (H_K + 3 * 9216)};
    const uint32_t vB[4] = {smb + 2u * (H_V + 0 * 9216), smb + 2u * (H_V + 1 * 9216),
                            smb + 2u * (H_V + 2 * 9216), smb + 2u * (H_V + 3 * 9216)};

    // ---- prologue: Q (into V slot 0) + first K tiles ----
    stage(H_V, Qh, 0);
    CP_COMMIT();
    stage(H_K + 0 * 9216, Kh, 1);
    CP_COMMIT();
    stage(H_K + 1 * 9216, Kh + TN * HD, 1);
    CP_COMMIT();
    CP_WAIT(1);  // Q + K0 landed (K1 may fly)
    __syncthreads();

    // hoist Q fragments
    uint32_t qf[4][2][4];
#pragma unroll
    for (int kk = 0; kk < 4; ++kk)
#pragma unroll
        for (int i = 0; i < 2; ++i)
            ldsm4(qf[kk][i][0], qf[kk][i][1], qf[kk][i][2], qf[kk][i][3],
                  vB[0] + (uint32_t)(wq + i * 16) * 144u + pa72 + kk * 32u);

    // rowsums from kernel A
    float lr[2][2];
#pragma unroll
    for (int i = 0; i < 2; ++i)
#pragma unroll
        for (int h = 0; h < 2; ++h)
            lr[i][h] = -log2f(g_RS[b * SEQ + q0 + wq + i * 16 + h * 8 + g]);

    __syncthreads();  // all warps hoisted Q before V0 overwrites it
    stage(H_V + 0 * 9216, Vh, 1);
    CP_COMMIT();
    stage(H_V + 1 * 9216, Vh + TN * HD, 1);
    CP_COMMIT();
    CP_WAIT(0);
    __syncthreads();

    float c[2][8][4];
    auto qk_issue = [&](uint32_t kbuf) {
#pragma unroll
        for (int kk = 0; kk < 4; ++kk) {
#pragma unroll
            for (int j2 = 0; j2 < 8; j2 += 2) {
                uint32_t b0, b1, b2_, b3_;
                ldsm4(b0, b1, b2_, b3_, kbuf + kq_off + (uint32_t)j2 * 1152u + kk * 32u);
                if (kk == 0) {
                    mma16_z(c[0][j2], qf[0][0], b0, b1);
                    mma16_z(c[1][j2], qf[0][1], b0, b1);
                    mma16_z(c[0][j2 + 1], qf[0][0], b2_, b3_);
                    mma16_z(c[1][j2 + 1], qf[0][1], b2_, b3_);
                } else {
                    mma16(c[0][j2], qf[kk][0], b0, b1);
                    mma16(c[1][j2], qf[kk][1], b0, b1);
                    mma16(c[0][j2 + 1], qf[kk][0], b2_, b3_);
                    mma16(c[1][j2 + 1], qf[kk][1], b2_, b3_);
                }
            }
        }
    };

    float o[2][8][4] = {};
    qk_issue(kB[0]);

    uint32_t a[4][2][4];
    // AV for a single kk — preserves o accumulation chain order when called kk=0..3
    auto av_kk = [&](uint32_t vb, int kk) {
#pragma unroll
        for (int j = 0; j < 4; ++j) {
            uint32_t b0, b1, b2_, b3_;
            ldsm4t(b0, b1, b2_, b3_, vb + va_off + (uint32_t)kk * 2304u + j * 32u);
            mma16(o[0][2 * j], a[kk][0], b0, b1);
            mma16(o[1][2 * j], a[kk][1], b0, b1);
            mma16(o[0][2 * j + 1], a[kk][0], b2_, b3_);
            mma16(o[1][2 * j + 1], a[kk][1], b2_, b3_);
        }
    };

    for (int it = 0; it < NIT; ++it) {
        const int n0 = it * TN;
        const uint32_t vb = vB[it & 3];
        // --- pre-barrier: stage(it+2); per-kk {exp, attn STG, pack, AV} ---
        if (it + 2 < NIT) {
            stage(H_K + ((it + 2) & 3) * 9216, Kh + (it + 2) * TN * HD, 1);
            stage(H_V + ((it + 2) & 3) * 9216, Vh + (it + 2) * TN * HD, 1);
            CP_COMMIT();
        }
        float* ar0[2];
        float* ar1[2];
#pragma unroll
        for (int i = 0; i < 2; ++i) {
            const int row = q0 + wq + i * 16 + g;
            ar0[i] = attnp + ((size_t)b * SEQ + row) * SEQ + n0 + wnq + 4 * tg;
            ar1[i] = ar0[i] + (size_t)8 * SEQ;
        }
#pragma unroll
        for (int kk = 0; kk < 4; ++kk) {
#pragma unroll
            for (int i = 0; i < 2; ++i) {
                c[i][2 * kk][0] = exp2f(c[i][2 * kk][0] + lr[i][0]);
                c[i][2 * kk][1] = exp2f(c[i][2 * kk][1] + lr[i][0]);
                c[i][2 * kk][2] = exp2f(c[i][2 * kk][2] + lr[i][1]);
                c[i][2 * kk][3] = exp2f(c[i][2 * kk][3] + lr[i][1]);
                c[i][2 * kk + 1][0] = exp2f(c[i][2 * kk + 1][0] + lr[i][0]);
                c[i][2 * kk + 1][1] = exp2f(c[i][2 * kk + 1][1] + lr[i][0]);
                c[i][2 * kk + 1][2] = exp2f(c[i][2 * kk + 1][2] + lr[i][1]);
                c[i][2 * kk + 1][3] = exp2f(c[i][2 * kk + 1][3] + lr[i][1]);
                __stcs(reinterpret_cast<float4*>(ar0[i] + 16 * kk),
                       make_float4(c[i][2 * kk][0], c[i][2 * kk][1],
                                   c[i][2 * kk + 1][0], c[i][2 * kk + 1][1]));
                __stcs(reinterpret_cast<float4*>(ar1[i] + 16 * kk),
                       make_float4(c[i][2 * kk][2], c[i][2 * kk][3],
                                   c[i][2 * kk + 1][2], c[i][2 * kk + 1][3]));
                a[kk][i][0] = f2h2(c[i][2 * kk][0], c[i][2 * kk][1]);
                a[kk][i][1] = f2h2(c[i][2 * kk][2], c[i][2 * kk][3]);
                a[kk][i][2] = f2h2(c[i][2 * kk + 1][0], c[i][2 * kk + 1][1]);
                a[kk][i][3] = f2h2(c[i][2 * kk + 1][2], c[i][2 * kk + 1][3]);
            }
            if (kk < 3) av_kk(vb, kk);  // AV interleaved with next kk's exp burst
        }
        if (it + 2 < NIT) CP_WAIT(1); else CP_WAIT(0);
        __syncthreads();
        // --- post-barrier: next QK first (c dead), AV tail fills its latency ---
        if (it + 1 < NIT) qk_issue(kB[(it + 1) & 3]);
        av_kk(vb, 3);
    }

    // ---- epilogue: reduce partial O across the 2 n-groups, write out ----
    float* FS = reinterpret_cast<float*>(sh);  // reuse K ring
    const int qg = w >> 1;
    __syncthreads();
    if (w & 1) {
#pragma unroll
        for (int i = 0; i < 2; ++i)
#pragma unroll
            for (int j = 0; j < 8; ++j) {
                const int col = j * 8 + 2 * tg;
                *reinterpret_cast<float2*>(&FS[qg * 2048 + (i * 16 + g) * 64 + col]) =
                    make_float2(o[i][j][0], o[i][j][1]);
                *reinterpret_cast<float2*>(&FS[qg * 2048 + (i * 16 + 8 + g) * 64 + col]) =
                    make_float2(o[i][j][2], o[i][j][3]);
            }
    }
    __syncthreads();
    if (!(w & 1)) {
#pragma unroll
        for (int i = 0; i < 2; ++i) {
            const int row = q0 + wq + i * 16 + g;
            float* orow = outp + ((size_t)b * SEQ + row) * HD;
#pragma unroll
            for (int j = 0; j < 8; ++j) {
                const int col = j * 8 + 2 * tg;
                float2 p0 =
                    *reinterpret_cast<float2*>(&FS[qg * 2048 + (i * 16 + g) * 64 + col]);
                float2 p1 = *reinterpret_cast<float2*>(
                    &FS[qg * 2048 + (i * 16 + 8 + g) * 64 + col]);
                *reinterpret_cast<float2*>(orow + col) =
                    make_float2(o[i][j][0] + p0.x, o[i][j][1] + p0.y);
                *reinterpret_cast<float2*>(orow + 8 * HD + col) =
                    make_float2(o[i][j][2] + p1.x, o[i][j][3] + p1.y);
            }
        }
    }
}

extern "C" void kernel_launch(void* const* d_in, const int* in_sizes, int n_in,
                              void* d_out, int out_size) {
    const float* q = (const float*)d_in[0];
    const float* k = (const float*)d_in[1];
    const float* v = (const float*)d_in[2];
    float* outp = (float*)d_out;
    float* attnp = outp + (size_t)NBATCH * SEQ * HD;

    cvt_kernel<<<NBATCH * SEQ * HD / (256 * 4), 256>>>(q, k, v);

    cudaFuncSetAttribute(attn_sums_k, cudaFuncAttributeMaxDynamicSharedMemorySize,
                         SMEMA_BYTES);
    cudaFuncSetAttribute(attn_fused, cudaFuncAttributeMaxDynamicSharedMemorySize,
                         SMEMB_BYTES);

    attn_sums_k<<<NBATCH * 64, 128, SMEMA_BYTES>>>();
    attn_fused<<<NBATCH * 32, NTH, SMEMB_BYTES>>>(outp, attnp);
}